// round 16
// baseline (speedup 1.0000x reference)
#include <cuda_runtime.h>
#include <cstdint>

#define F        512
#define SPLIT    16384
#define NLIL     2048
#define NLAYERS  8
#define NMLIL    8
#define MTOT     (SPLIT + NMLIL * NLIL)   /* 32768 */

#define BM   128
#define BN   128
#define KC   32
#define NCH  (F / KC)                     /* 16 chunks */

#define LDSW 36                           /* words per smem row (32 + pad 4) */
#define TILE_BYTES (BM * LDSW * 4)        /* 18432 */
#define OFF_AH 0
#define OFF_AL (TILE_BYTES)
#define OFF_B  (2 * TILE_BYTES)
#define STAGE_BYTES (3 * TILE_BYTES)      /* 55296 */
#define SMEM_DYN (2 * STAGE_BYTES)        /* 110592 -> 2 CTAs/SM */

__device__ float g_ping[(size_t)MTOT * F];
__device__ float g_pong[(size_t)MTOT * F];
/* k-permuted weights: big (transposed to [g][f]) and little (already [g][f]) */
__device__ float g_WTp[(size_t)NLAYERS * F * F];
__device__ float g_Wlp[(size_t)NLAYERS * NMLIL * F * F];

/* ---------------- helpers ---------------- */
__device__ __forceinline__ uint32_t smem_u32(const void* p) {
    uint32_t a;
    asm("{ .reg .u64 t; cvta.to.shared.u64 t, %1; cvt.u32.u64 %0, t; }" : "=r"(a) : "l"(p));
    return a;
}
__device__ __forceinline__ void cpasync16(uint32_t s, const void* g) {
    asm volatile("cp.async.cg.shared.global [%0], [%1], 16;" :: "r"(s), "l"(g) : "memory");
}
#define CP_COMMIT() asm volatile("cp.async.commit_group;" ::: "memory")
#define CP_WAIT0()  asm volatile("cp.async.wait_group 0;" ::: "memory")

__device__ __forceinline__ float tf32_rna(float v) {
    uint32_t h;
    asm("cvt.rna.tf32.f32 %0, %1;" : "=r"(h) : "f"(v));
    return __uint_as_float(h);
}
__device__ __forceinline__ void split_tf32(float v, uint32_t& h, uint32_t& l) {
    asm("cvt.rna.tf32.f32 %0, %1;" : "=r"(h) : "f"(v));
    float lo = v - __uint_as_float(h);
    asm("cvt.rna.tf32.f32 %0, %1;" : "=r"(l) : "f"(lo));
}
__device__ __forceinline__ void mma8(float* c, const uint32_t* a, uint32_t b0, uint32_t b1) {
    asm volatile(
        "mma.sync.aligned.m16n8k8.row.col.f32.tf32.tf32.f32 "
        "{%0,%1,%2,%3}, {%4,%5,%6,%7}, {%8,%9}, {%0,%1,%2,%3};"
        : "+f"(c[0]), "+f"(c[1]), "+f"(c[2]), "+f"(c[3])
        : "r"(a[0]), "r"(a[1]), "r"(a[2]), "r"(a[3]), "r"(b0), "r"(b1));
}

/* -------- prep: Wbig transpose + k-permute: WTp[l][g][perm(f)] = W[l][f][g] -------- */
__global__ void permute_wbig_T(const float* __restrict__ W, float* __restrict__ WT) {
    __shared__ float t[32][33];
    int l = blockIdx.z;
    int f0 = blockIdx.x * 32, g0 = blockIdx.y * 32;
    int x = threadIdx.x, y = threadIdx.y;
    const float* Wl = W + (size_t)l * F * F;
    float* WTl = WT + (size_t)l * F * F;
#pragma unroll
    for (int r = 0; r < 32; r += 8)
        t[y + r][x] = Wl[(size_t)(f0 + y + r) * F + g0 + x];
    __syncthreads();
    const int xp = (x & 3) * 8 + (x >> 2);     /* within-chunk k permute */
#pragma unroll
    for (int r = 0; r < 32; r += 8)
        WTl[(size_t)(g0 + y + r) * F + f0 + xp] = t[x][y + r];
}

/* -------- prep: Wlil k-permute (layout already [g][f]) -------- */
__global__ void permute_lil(const float* __restrict__ in, float* __restrict__ out, int n4) {
    int i = blockIdx.x * blockDim.x + threadIdx.x;
    if (i >= n4) return;
    float4 v = ((const float4*)in)[i];
    const int chunk = i >> 3;          /* 32-float chunk index */
    const int c = i & 7;               /* input float4 within chunk: k = 4c+j */
    float* o = out + (size_t)chunk * 32;
    o[0 * 8 + c] = v.x;                /* p(k) = (k%4)*8 + k/4 = j*8 + c */
    o[1 * 8 + c] = v.y;
    o[2 * 8 + c] = v.z;
    o[3 * 8 + c] = v.w;
}

/* ------------------------- per-layer GEMM ------------------------- */
__global__ __launch_bounds__(256, 2)
void layer_kernel(const float* __restrict__ src, float* __restrict__ dst,
                  const float* __restrict__ WTp, const float* __restrict__ Bbig,
                  const float* __restrict__ Wlp, const float* __restrict__ Blil,
                  int layer)
{
    extern __shared__ char smemb[];
    const int tid  = threadIdx.x;
    const int warp = tid >> 5;
    const int lane = tid & 31;
    const int wm   = warp >> 2;         /* 0..1 : 64-row slab  */
    const int wn   = warp & 3;          /* 0..3 : 32-col slab  */
    const int row0 = blockIdx.x * BM;
    const int n0   = blockIdx.y * BN;

    const float* wsrc;
    const float* bias;
    if (row0 < SPLIT) {
        wsrc = WTp + (size_t)layer * F * F + (size_t)n0 * F;
        bias = Bbig + layer * F + n0;
    } else {
        int mi = (row0 - SPLIT) / NLIL;
        wsrc = Wlp + (size_t)(layer * NMLIL + mi) * F * F + (size_t)n0 * F;
        bias = Blil + (layer * NMLIL + mi) * F + n0;
    }
    const float* asrc = src + (size_t)row0 * F;

    const uint32_t sb = smem_u32(smemb);

    /* --- A staging: one thread per row-half (32 rows/warp) --- */
    const int sra = tid & 127;                  /* row 0..127 */
    const int sha = tid >> 7;                   /* 16-float half */
    const float* gA = asrc + (size_t)sra * F + sha * 16;

    /* --- B staging (cp.async, permuted global): thread pair per row --- */
    const int srb = tid >> 1;
    const int shb = tid & 1;
    const float* gB = wsrc + (size_t)srb * F + shb * 16;
    const uint32_t dofsB = OFF_B + (srb * LDSW + shb * 16) * 4;

    float4 pa[4];

    auto issueB = [&](int t) {
        const uint32_t d = sb + (t & 1) * STAGE_BYTES + dofsB;
        const float* g = gB + t * KC;
#pragma unroll
        for (int c = 0; c < 4; ++c)
            cpasync16(d + c * 16, g + c * 4);
        CP_COMMIT();
    };
    auto ldgA = [&](int t) {
        const int k0 = t * KC;
#pragma unroll
        for (int c = 0; c < 4; ++c)
            pa[c] = *(const float4*)(gA + k0 + c * 4);
    };
    auto stsA = [&](int t) {    /* split + permuted store: j-major STS.128 */
        char* st = smemb + (t & 1) * STAGE_BYTES;
        uint32_t* AHw = (uint32_t*)(st + OFF_AH);
        uint32_t* ALw = (uint32_t*)(st + OFF_AL);
        uint32_t h[4][4], l[4][4];              /* [c][j] */
#pragma unroll
        for (int c = 0; c < 4; ++c) {
            split_tf32(pa[c].x, h[c][0], l[c][0]);
            split_tf32(pa[c].y, h[c][1], l[c][1]);
            split_tf32(pa[c].z, h[c][2], l[c][2]);
            split_tf32(pa[c].w, h[c][3], l[c][3]);
        }
        const int base = sra * LDSW + 4 * sha;  /* p(k)=j*8+(4*sha+c) */
#pragma unroll
        for (int j = 0; j < 4; ++j) {
            uint4 hv; hv.x = h[0][j]; hv.y = h[1][j]; hv.z = h[2][j]; hv.w = h[3][j];
            uint4 lv; lv.x = l[0][j]; lv.y = l[1][j]; lv.z = l[2][j]; lv.w = l[3][j];
            *(uint4*)&AHw[base + j * 8] = hv;
            *(uint4*)&ALw[base + j * 8] = lv;
        }
    };

    float acc[4][4][4];
#pragma unroll
    for (int i = 0; i < 4; ++i)
#pragma unroll
        for (int j = 0; j < 4; ++j) {
            acc[i][j][0] = 0.f; acc[i][j][1] = 0.f;
            acc[i][j][2] = 0.f; acc[i][j][3] = 0.f;
        }

    const int lr = lane >> 2;   /* 0..7 */
    const int lc = lane & 3;    /* 0..3 */

    /* prologue */
    issueB(0);
    ldgA(0);
    stsA(0);
    CP_WAIT0();
    __syncthreads();

    for (int t = 0; t < NCH; ++t) {
        if (t + 1 < NCH) { issueB(t + 1); ldgA(t + 1); }

        const char* st = smemb + (t & 1) * STAGE_BYTES;
        const uint32_t* AH = (const uint32_t*)(st + OFF_AH);
        const uint32_t* AL = (const uint32_t*)(st + OFF_AL);
        const float*    Bs = (const float*)(st + OFF_B);

#pragma unroll
        for (int ks = 0; ks < 4; ++ks) {
            /* A fragments: permuted layout -> one LDS.64 per row per tile */
            uint32_t ah[4][4], al[4][4];
#pragma unroll
            for (int mt = 0; mt < 4; ++mt) {
                const int r0 = wm * 64 + mt * 16 + lr;
                const int w0 = r0 * LDSW + lc * 8 + ks * 2;
                const int w1 = w0 + 8 * LDSW;
                const uint2 h0 = *(const uint2*)&AH[w0];
                const uint2 h1 = *(const uint2*)&AH[w1];
                const uint2 l0 = *(const uint2*)&AL[w0];
                const uint2 l1 = *(const uint2*)&AL[w1];
                ah[mt][0] = h0.x; ah[mt][1] = h1.x; ah[mt][2] = h0.y; ah[mt][3] = h1.y;
                al[mt][0] = l0.x; al[mt][1] = l1.x; al[mt][2] = l0.y; al[mt][3] = l1.y;
            }
#pragma unroll
            for (int nt = 0; nt < 4; ++nt) {
                const int nr = wn * 32 + nt * 8 + lr;
                const float2 u = *(const float2*)&Bs[nr * LDSW + lc * 8 + ks * 2];
                uint32_t bh0, bl0, bh1, bl1;
                split_tf32(u.x, bh0, bl0);
                split_tf32(u.y, bh1, bl1);
                /* term-outer, mt-inner: consecutive MMAs hit different accs */
#pragma unroll
                for (int mt = 0; mt < 4; ++mt) mma8(acc[mt][nt], ah[mt], bh0, bh1);
#pragma unroll
                for (int mt = 0; mt < 4; ++mt) mma8(acc[mt][nt], al[mt], bh0, bh1);
#pragma unroll
                for (int mt = 0; mt < 4; ++mt) mma8(acc[mt][nt], ah[mt], bl0, bl1);
            }
        }

        if (t + 1 < NCH) {
            stsA(t + 1);        /* other buffer: safe w.r.t. readers of t */
            CP_WAIT0();         /* B(t+1) landed */
        }
        __syncthreads();
    }

    /* ---------------- epilogue: bias + store ---------------- */
#pragma unroll
    for (int mt = 0; mt < 4; ++mt) {
        const int r = row0 + wm * 64 + mt * 16 + lr;
#pragma unroll
        for (int nt = 0; nt < 4; ++nt) {
            const int nloc = wn * 32 + nt * 8 + lc * 2;
            const float bx = bias[nloc];
            const float by = bias[nloc + 1];
            float2 o0, o1;
            o0.x = acc[mt][nt][0] + bx; o0.y = acc[mt][nt][1] + by;
            o1.x = acc[mt][nt][2] + bx; o1.y = acc[mt][nt][3] + by;
            *(float2*)(dst + (size_t)r * F + n0 + nloc)       = o0;
            *(float2*)(dst + (size_t)(r + 8) * F + n0 + nloc) = o1;
        }
    }
}

/* ------------------------------ host ------------------------------ */
extern "C" void kernel_launch(void* const* d_in, const int* in_sizes, int n_in,
                              void* d_out, int out_size)
{
    const float* x    = (const float*)d_in[0];
    const float* Wbig = (const float*)d_in[1];
    const float* Bbig = (const float*)d_in[2];
    const float* Wlil = (const float*)d_in[3];
    const float* Blil = (const float*)d_in[4];
    float* out = (float*)d_out;

    float *ping, *pong, *wtp, *wlp;
    cudaGetSymbolAddress((void**)&ping, g_ping);
    cudaGetSymbolAddress((void**)&pong, g_pong);
    cudaGetSymbolAddress((void**)&wtp, g_WTp);
    cudaGetSymbolAddress((void**)&wlp, g_Wlp);

    cudaFuncSetAttribute(layer_kernel,
                         cudaFuncAttributeMaxDynamicSharedMemorySize, SMEM_DYN);

    /* prep: transpose+permute big weights, permute little weights */
    permute_wbig_T<<<dim3(16, 16, 8), dim3(32, 8)>>>(Wbig, wtp);
    {
        int n4 = (NLAYERS * NMLIL * F * F) / 4;
        permute_lil<<<(n4 + 255) / 256, 256>>>(Wlil, wlp, n4);
    }

    dim3 grid(MTOT / BM, F / BN);   /* 256 x 4 */
    for (int l = 0; l < NLAYERS; ++l) {
        const float* s = (l == 0) ? x : ((l & 1) ? ping : pong);
        float* d = (l == NLAYERS - 1) ? out : ((l & 1) ? pong : ping);
        layer_kernel<<<grid, 256, SMEM_DYN>>>(s, d, wtp, Bbig, wlp, Blil, l);
    }
}

// round 17
// speedup vs baseline: 1.9750x; 1.9750x over previous
#include <cuda_runtime.h>
#include <cstdint>

#define F        512
#define SPLIT    16384
#define NLIL     2048
#define NLAYERS  8
#define NMLIL    8
#define MTOT     (SPLIT + NMLIL * NLIL)   /* 32768 */

#define BM   128
#define BN   128
#define KC   32
#define NCH  (F / KC)                     /* 16 chunks */

#define LDSW 36                           /* words per smem row (32 + pad 4) */
#define TILE_BYTES (BM * LDSW * 4)        /* 18432 */
#define OFF_AH 0
#define OFF_AL (TILE_BYTES)
#define OFF_B  (2 * TILE_BYTES)
#define STAGE_BYTES (3 * TILE_BYTES)      /* 55296 */
#define SMEM_DYN (2 * STAGE_BYTES)        /* 110592 -> 2 CTAs/SM */

__device__ float g_ping[(size_t)MTOT * F];
__device__ float g_pong[(size_t)MTOT * F];
__device__ float g_WT[(size_t)NLAYERS * F * F];

/* ---------------- helpers ---------------- */
__device__ __forceinline__ uint32_t smem_u32(const void* p) {
    uint32_t a;
    asm("{ .reg .u64 t; cvta.to.shared.u64 t, %1; cvt.u32.u64 %0, t; }" : "=r"(a) : "l"(p));
    return a;
}
__device__ __forceinline__ void cpasync16(uint32_t s, const void* g) {
    asm volatile("cp.async.cg.shared.global [%0], [%1], 16;" :: "r"(s), "l"(g) : "memory");
}
#define CP_COMMIT() asm volatile("cp.async.commit_group;" ::: "memory")
#define CP_WAIT0()  asm volatile("cp.async.wait_group 0;" ::: "memory")

/* mask split: hi = RZ-tf32(v) via mask, lo = exact residual (HW truncates at MMA) */
__device__ __forceinline__ void msplit(float v, uint32_t& h, uint32_t& l) {
    uint32_t hv = __float_as_uint(v) & 0xFFFFE000u;
    h = hv;
    l = __float_as_uint(v - __uint_as_float(hv));
}
__device__ __forceinline__ void mma8(float* c, const uint32_t* a, uint32_t b0, uint32_t b1) {
    asm volatile(
        "mma.sync.aligned.m16n8k8.row.col.f32.tf32.tf32.f32 "
        "{%0,%1,%2,%3}, {%4,%5,%6,%7}, {%8,%9}, {%0,%1,%2,%3};"
        : "+f"(c[0]), "+f"(c[1]), "+f"(c[2]), "+f"(c[3])
        : "r"(a[0]), "r"(a[1]), "r"(a[2]), "r"(a[3]), "r"(b0), "r"(b1));
}
__device__ __forceinline__ void ldsm_x4(uint32_t* r, uint32_t a) {
    asm volatile("ldmatrix.sync.aligned.m8n8.x4.shared.b16 {%0,%1,%2,%3}, [%4];"
                 : "=r"(r[0]), "=r"(r[1]), "=r"(r[2]), "=r"(r[3]) : "r"(a));
}
__device__ __forceinline__ void ldsm_x2(uint32_t& r0, uint32_t& r1, uint32_t a) {
    asm volatile("ldmatrix.sync.aligned.m8n8.x2.shared.b16 {%0,%1}, [%2];"
                 : "=r"(r0), "=r"(r1) : "r"(a));
}

/* -------- Wbig transpose: WT[l][g][f] = W[l][f][g] (so B is [N,K]) -------- */
__global__ void transpose_wbig(const float* __restrict__ W, float* __restrict__ WT) {
    __shared__ float t[32][33];
    int l = blockIdx.z;
    int f0 = blockIdx.x * 32, g0 = blockIdx.y * 32;
    int x = threadIdx.x, y = threadIdx.y;
    const float* Wl = W + (size_t)l * F * F;
    float* WTl = WT + (size_t)l * F * F;
#pragma unroll
    for (int r = 0; r < 32; r += 8)
        t[y + r][x] = Wl[(size_t)(f0 + y + r) * F + g0 + x];
    __syncthreads();
#pragma unroll
    for (int r = 0; r < 32; r += 8)
        WTl[(size_t)(g0 + y + r) * F + f0 + x] = t[x][y + r];
}

/* ------------------------- per-layer GEMM ------------------------- */
__global__ __launch_bounds__(256, 2)
void layer_kernel(const float* __restrict__ src, float* __restrict__ dst,
                  const float* __restrict__ WT, const float* __restrict__ Bbig,
                  const float* __restrict__ Wlil, const float* __restrict__ Blil,
                  int layer)
{
    extern __shared__ char smemb[];
    const int tid  = threadIdx.x;
    const int warp = tid >> 5;
    const int lane = tid & 31;
    const int wm   = warp >> 2;         /* 0..1 : 64-row slab  */
    const int wn   = warp & 3;          /* 0..3 : 32-col slab  */
    const int row0 = blockIdx.x * BM;
    const int n0   = blockIdx.y * BN;

    const float* wsrc;
    const float* bias;
    if (row0 < SPLIT) {
        wsrc = WT + (size_t)layer * F * F + (size_t)n0 * F;
        bias = Bbig + layer * F + n0;
    } else {
        int mi = (row0 - SPLIT) / NLIL;
        wsrc = Wlil + (size_t)(layer * NMLIL + mi) * F * F + (size_t)n0 * F;
        bias = Blil + (layer * NMLIL + mi) * F + n0;
    }
    const float* asrc = src + (size_t)row0 * F;

    const uint32_t sb = smem_u32(smemb);

    /* --- staging coordinates (R12-proven): thread pair per row --- */
    const int srow = tid >> 1;                  /* 0..127 */
    const int shf  = (tid & 1) * 16;            /* float offset within 32-col row */
    const float* gA = asrc + (size_t)srow * F + shf;
    const float* gB = wsrc + (size_t)srow * F + shf;
    const int sbase = srow * LDSW + shf;

    float4 pa[4];

    auto issueB = [&](int t) {                  /* cp.async raw fp32 B tile */
        const int k0 = t * KC;
        const uint32_t d = sb + (t & 1) * STAGE_BYTES + OFF_B + sbase * 4;
#pragma unroll
        for (int c = 0; c < 4; ++c)
            cpasync16(d + c * 16, gB + k0 + c * 4);
        CP_COMMIT();
    };
    auto ldgA = [&](int t) {
        const int k0 = t * KC;
#pragma unroll
        for (int c = 0; c < 4; ++c)
            pa[c] = *(const float4*)(gA + k0 + c * 4);
    };
    auto stsA = [&](int t) {                    /* mask-split, store Ah/Al */
        char* st = smemb + (t & 1) * STAGE_BYTES;
        uint32_t* AH = (uint32_t*)(st + OFF_AH);
        uint32_t* AL = (uint32_t*)(st + OFF_AL);
#pragma unroll
        for (int c = 0; c < 4; ++c) {
            uint4 h, l;
            msplit(pa[c].x, h.x, l.x); msplit(pa[c].y, h.y, l.y);
            msplit(pa[c].z, h.z, l.z); msplit(pa[c].w, h.w, l.w);
            *(uint4*)(AH + sbase + c * 4) = h;
            *(uint4*)(AL + sbase + c * 4) = l;
        }
    };

    float acc[4][4][4];
#pragma unroll
    for (int i = 0; i < 4; ++i)
#pragma unroll
        for (int j = 0; j < 4; ++j) {
            acc[i][j][0] = 0.f; acc[i][j][1] = 0.f;
            acc[i][j][2] = 0.f; acc[i][j][3] = 0.f;
        }

    const int lr = lane >> 2;   /* 0..7 */
    const int lc = lane & 3;    /* 0..3 */

    /* ldmatrix per-lane address components */
    const int l8  = lane & 7;
    const int l16 = (lane >> 3) & 1;
    const int lhi = lane >> 4;
    /* A x4: tile0 rows 0-7 kb, tile1 rows 8-15 kb, tile2 rows 0-7 kb+4, tile3 rows 8-15 kb+4 */
    const uint32_t aAddrBase = ((wm * 64 + l16 * 8 + l8) * LDSW + lhi * 4) * 4;
    /* B x2: tile0 n-rows kb, tile1 n-rows kb+4 (lanes 0-15 supply addrs) */
    const uint32_t bAddrBase = OFF_B + ((wn * 32 + l8) * LDSW + l16 * 4) * 4;

    /* prologue */
    issueB(0);
    ldgA(0);
    stsA(0);
    CP_WAIT0();
    __syncthreads();

    for (int t = 0; t < NCH; ++t) {
        if (t + 1 < NCH) { issueB(t + 1); ldgA(t + 1); }

        const uint32_t stg = sb + (t & 1) * STAGE_BYTES;
        const uint32_t aAddr = stg + aAddrBase;
        const uint32_t bAddr = stg + bAddrBase;

#pragma unroll
        for (int ks = 0; ks < 4; ++ks) {
            const uint32_t ksb = ks * 32;       /* 8 floats per k8-step */
            /* A fragments via ldmatrix: 1 LDSM.x4 per (tile, term) */
            uint32_t ah[4][4], al[4][4];
#pragma unroll
            for (int mt = 0; mt < 4; ++mt) {
                const uint32_t a0 = aAddr + mt * (16 * LDSW * 4) + ksb;
                ldsm_x4(ah[mt], a0);
                ldsm_x4(al[mt], a0 + TILE_BYTES);
            }
#pragma unroll
            for (int nt = 0; nt < 4; ++nt) {
                uint32_t u0, u1;
                ldsm_x2(u0, u1, bAddr + nt * (8 * LDSW * 4) + ksb);
                uint32_t bh0, bl0, bh1, bl1;
                msplit(__uint_as_float(u0), bh0, bl0);
                msplit(__uint_as_float(u1), bh1, bl1);
                /* term-outer, mt-inner: consecutive MMAs hit different accs */
#pragma unroll
                for (int mt = 0; mt < 4; ++mt) mma8(acc[mt][nt], ah[mt], bh0, bh1);
#pragma unroll
                for (int mt = 0; mt < 4; ++mt) mma8(acc[mt][nt], al[mt], bh0, bh1);
#pragma unroll
                for (int mt = 0; mt < 4; ++mt) mma8(acc[mt][nt], ah[mt], bl0, bl1);
            }
        }

        if (t + 1 < NCH) {
            stsA(t + 1);        /* other buffer: safe w.r.t. readers of t */
            CP_WAIT0();         /* B(t+1) landed */
        }
        __syncthreads();
    }

    /* ---------------- epilogue: bias + store ---------------- */
#pragma unroll
    for (int mt = 0; mt < 4; ++mt) {
        const int r = row0 + wm * 64 + mt * 16 + lr;
#pragma unroll
        for (int nt = 0; nt < 4; ++nt) {
            const int nloc = wn * 32 + nt * 8 + lc * 2;
            const float bx = bias[nloc];
            const float by = bias[nloc + 1];
            float2 o0, o1;
            o0.x = acc[mt][nt][0] + bx; o0.y = acc[mt][nt][1] + by;
            o1.x = acc[mt][nt][2] + bx; o1.y = acc[mt][nt][3] + by;
            *(float2*)(dst + (size_t)r * F + n0 + nloc)       = o0;
            *(float2*)(dst + (size_t)(r + 8) * F + n0 + nloc) = o1;
        }
    }
}

/* ------------------------------ host ------------------------------ */
extern "C" void kernel_launch(void* const* d_in, const int* in_sizes, int n_in,
                              void* d_out, int out_size)
{
    const float* x    = (const float*)d_in[0];
    const float* Wbig = (const float*)d_in[1];
    const float* Bbig = (const float*)d_in[2];
    const float* Wlil = (const float*)d_in[3];
    const float* Blil = (const float*)d_in[4];
    float* out = (float*)d_out;

    float *ping, *pong, *wt;
    cudaGetSymbolAddress((void**)&ping, g_ping);
    cudaGetSymbolAddress((void**)&pong, g_pong);
    cudaGetSymbolAddress((void**)&wt, g_WT);

    cudaFuncSetAttribute(layer_kernel,
                         cudaFuncAttributeMaxDynamicSharedMemorySize, SMEM_DYN);

    transpose_wbig<<<dim3(16, 16, 8), dim3(32, 8)>>>(Wbig, wt);

    dim3 grid(MTOT / BM, F / BN);   /* 256 x 4 */
    for (int l = 0; l < NLAYERS; ++l) {
        const float* s = (l == 0) ? x : ((l & 1) ? ping : pong);
        float* d = (l == NLAYERS - 1) ? out : ((l & 1) ? pong : ping);
        layer_kernel<<<grid, 256, SMEM_DYN>>>(s, d, wt, Bbig, Wlil, Blil, l);
    }
}